// round 15
// baseline (speedup 1.0000x reference)
#include <cuda_runtime.h>
#include <cuda_bf16.h>
#include <math.h>

#define HEADS    8
#define ROW      256         // HEADS * 32 floats, both k and v rows
#define N_MAX    32768
#define SLOTS    256         // bucket slots per node (max expected degree ~55)
#define CAPX     320         // smem edge-id capacity
#define LSTR     9           // padded logit stride (gcd(9,32)=1 -> conflict-free)
#define OVF_MAX  8192

// Static device scratch (zero-initialized at module load; k_attn self-cleans
// g_count / g_ovf_cnt AFTER its first barrier so every launch starts zeroed).
__device__ int g_count[N_MAX];
__device__ int g_edges[(size_t)N_MAX * SLOTS];   // 20 MB bucketed edge ids
__device__ int g_ovf_cnt;
__device__ int g_ovf[OVF_MAX];

// ---------------- bucket build (single pass, 4 edges/thread) ----------------

__global__ void k_scatter(const int* __restrict__ dst, int E) {
    int i = (blockIdx.x * blockDim.x + threadIdx.x) * 4;
    if (i + 3 < E) {
        int4 d = *(const int4*)(dst + i);
        int p0 = atomicAdd(&g_count[d.x], 1);
        int p1 = atomicAdd(&g_count[d.y], 1);
        int p2 = atomicAdd(&g_count[d.z], 1);
        int p3 = atomicAdd(&g_count[d.w], 1);
        if (p0 < SLOTS) g_edges[(size_t)d.x * SLOTS + p0] = i;
        else { int o = atomicAdd(&g_ovf_cnt, 1); if (o < OVF_MAX) g_ovf[o] = i; }
        if (p1 < SLOTS) g_edges[(size_t)d.y * SLOTS + p1] = i + 1;
        else { int o = atomicAdd(&g_ovf_cnt, 1); if (o < OVF_MAX) g_ovf[o] = i + 1; }
        if (p2 < SLOTS) g_edges[(size_t)d.z * SLOTS + p2] = i + 2;
        else { int o = atomicAdd(&g_ovf_cnt, 1); if (o < OVF_MAX) g_ovf[o] = i + 2; }
        if (p3 < SLOTS) g_edges[(size_t)d.w * SLOTS + p3] = i + 3;
        else { int o = atomicAdd(&g_ovf_cnt, 1); if (o < OVF_MAX) g_ovf[o] = i + 3; }
    } else {
        for (int j = i; j < E; j++) {
            int d = dst[j];
            int p = atomicAdd(&g_count[d], 1);
            if (p < SLOTS) g_edges[(size_t)d * SLOTS + p] = j;
            else { int o = atomicAdd(&g_ovf_cnt, 1); if (o < OVF_MAX) g_ovf[o] = j; }
        }
    }
}

// ---------------- Main attention kernel ----------------
// One block (256 thr) per destination node. Locked best configuration:
// Phase 1: warp-per-edge logits, 2-deep unroll (4x LDG.128 in flight/warp),
//          2-shfl segmented reduce vs register-resident q (loaded at the
//          very top of the kernel, before the prologue chain).
// Phase 2: single-pass softmax (no max subtraction: logits bounded ~|2.5|,
//          softmax is shift-invariant -> mathematically identical).
// Phase 3: float4-column value accumulation, 4-deep unroll, smem combine.
// Prologue: eid fill vectorized with int4 (buckets are 1KB-aligned).

__global__ __launch_bounds__(256, 8)
void k_attn(const float* __restrict__ v, const float* __restrict__ kk,
            const float* __restrict__ q, const int* __restrict__ dst,
            float* __restrict__ out) {
    const int n   = blockIdx.x;
    const int tid = threadIdx.x;
    const int w   = tid >> 5;
    const int l   = tid & 31;

    __shared__ __align__(16) int s_eid[CAPX];
    __shared__ float  s_lg[CAPX * LSTR];
    __shared__ float4 s_red[256];
    __shared__ float  s_inv[HEADS];
    __shared__ int    s_novf;

    // q row for this node, lane's 8-element slice (head = l>>2).
    // Issued FIRST: independent of everything, overlaps the prologue chain.
    const float* qp = q + (size_t)n * ROW + l * 8;
    const float4 q0 = *(const float4*)qp;
    const float4 q1 = *(const float4*)(qp + 4);

    const int cnt_raw = g_count[n];
    int cnt = (cnt_raw < SLOTS) ? cnt_raw : SLOTS;

    // Vectorized eid fill: buckets are 1KB-aligned, pull 4 ids per thread.
    {
        const int4* src = (const int4*)(g_edges + (size_t)n * SLOTS);
        int nvec = cnt >> 2;
        for (int j = tid; j < nvec; j += 256)
            ((int4*)s_eid)[j] = src[j];
        for (int j = (nvec << 2) + tid; j < cnt; j += 256)
            s_eid[j] = g_edges[(size_t)n * SLOTS + j];
    }

    if (__builtin_expect(cnt_raw > SLOTS, 0)) {
        // Overflow path: never taken for this data, kept for correctness.
        if (tid == 0) s_novf = 0;
        __syncthreads();
        int total = g_ovf_cnt;
        if (total > OVF_MAX) total = OVF_MAX;
        for (int o = tid; o < total; o += 256) {
            int e = g_ovf[o];
            if (dst[e] == n) {
                int p = atomicAdd(&s_novf, 1);
                if (cnt + p < CAPX) s_eid[cnt + p] = e;
            }
        }
        __syncthreads();
        int x = cnt + s_novf;
        cnt = (x < CAPX) ? x : CAPX;
    }
    __syncthreads();

    // Self-clean for next launch (all threads consumed g_count[n] already).
    if (tid == 0) {
        g_count[n] = 0;
        if (n == 0) g_ovf_cnt = 0;
    }

    // ---- Phase 1: logits (warp-per-edge, 2x LDG.128 + 2 shfl) ----
    {
        int j = w;
        for (; j + 8 < cnt; j += 16) {
            int ea = s_eid[j];
            int eb = s_eid[j + 8];
            const float4* ka = (const float4*)(kk + (size_t)ea * ROW + l * 8);
            const float4* kb = (const float4*)(kk + (size_t)eb * ROW + l * 8);
            float4 a0 = __ldcs(ka), a1 = __ldcs(ka + 1);
            float4 b0 = __ldcs(kb), b1 = __ldcs(kb + 1);
            float da = a0.x*q0.x + a0.y*q0.y + a0.z*q0.z + a0.w*q0.w
                     + a1.x*q1.x + a1.y*q1.y + a1.z*q1.z + a1.w*q1.w;
            float db = b0.x*q0.x + b0.y*q0.y + b0.z*q0.z + b0.w*q0.w
                     + b1.x*q1.x + b1.y*q1.y + b1.z*q1.z + b1.w*q1.w;
            da += __shfl_xor_sync(0xffffffffu, da, 1);
            da += __shfl_xor_sync(0xffffffffu, da, 2);
            db += __shfl_xor_sync(0xffffffffu, db, 1);
            db += __shfl_xor_sync(0xffffffffu, db, 2);
            if ((l & 3) == 0) {
                int h = l >> 2;
                s_lg[j * LSTR + h]       = da * 0.0625f;
                s_lg[(j + 8) * LSTR + h] = db * 0.0625f;
            }
        }
        for (; j < cnt; j += 8) {
            int e = s_eid[j];
            const float4* kr = (const float4*)(kk + (size_t)e * ROW + l * 8);
            float4 a0 = __ldcs(kr), a1 = __ldcs(kr + 1);
            float d = a0.x*q0.x + a0.y*q0.y + a0.z*q0.z + a0.w*q0.w
                    + a1.x*q1.x + a1.y*q1.y + a1.z*q1.z + a1.w*q1.w;
            d += __shfl_xor_sync(0xffffffffu, d, 1);
            d += __shfl_xor_sync(0xffffffffu, d, 2);
            if ((l & 3) == 0)
                s_lg[j * LSTR + (l >> 2)] = d * 0.0625f;
        }
    }
    __syncthreads();

    // ---- Phase 2: per-head softmax, single pass ----
    {
        float s = 0.f;
        for (int j = l; j < cnt; j += 32) {
            float e = __expf(s_lg[j * LSTR + w]);
            s_lg[j * LSTR + w] = e;
            s += e;
        }
        #pragma unroll
        for (int o = 16; o; o >>= 1)
            s += __shfl_xor_sync(0xffffffffu, s, o);
        if (l == 0) s_inv[w] = 1.f / fmaxf(s, 1e-9f);
    }
    __syncthreads();

    // ---- Phase 3: value accumulation (4 float4 loads in flight/thread) ----
    const int c  = tid & 63;   // float4 column within 256-float row
    const int eo = tid >> 6;   // edge offset 0..3
    const int h  = c >> 3;
    float4 acc = make_float4(0.f, 0.f, 0.f, 0.f);
    {
        int j = eo;
        for (; j + 12 < cnt; j += 16) {
            int e0 = s_eid[j];
            int e1 = s_eid[j + 4];
            int e2 = s_eid[j + 8];
            int e3 = s_eid[j + 12];
            float w0 = s_lg[j * LSTR + h];
            float w1 = s_lg[(j + 4) * LSTR + h];
            float w2 = s_lg[(j + 8) * LSTR + h];
            float w3 = s_lg[(j + 12) * LSTR + h];
            float4 v0 = __ldcs((const float4*)(v + (size_t)e0 * ROW + c * 4));
            float4 v1 = __ldcs((const float4*)(v + (size_t)e1 * ROW + c * 4));
            float4 v2 = __ldcs((const float4*)(v + (size_t)e2 * ROW + c * 4));
            float4 v3 = __ldcs((const float4*)(v + (size_t)e3 * ROW + c * 4));
            acc.x += w0 * v0.x + w1 * v1.x + w2 * v2.x + w3 * v3.x;
            acc.y += w0 * v0.y + w1 * v1.y + w2 * v2.y + w3 * v3.y;
            acc.z += w0 * v0.z + w1 * v1.z + w2 * v2.z + w3 * v3.z;
            acc.w += w0 * v0.w + w1 * v1.w + w2 * v2.w + w3 * v3.w;
        }
        for (; j + 4 < cnt; j += 8) {
            int ea = s_eid[j];
            int eb = s_eid[j + 4];
            float wa = s_lg[j * LSTR + h];
            float wb = s_lg[(j + 4) * LSTR + h];
            float4 va = __ldcs((const float4*)(v + (size_t)ea * ROW + c * 4));
            float4 vb = __ldcs((const float4*)(v + (size_t)eb * ROW + c * 4));
            acc.x += wa * va.x + wb * vb.x;
            acc.y += wa * va.y + wb * vb.y;
            acc.z += wa * va.z + wb * vb.z;
            acc.w += wa * va.w + wb * vb.w;
        }
        for (; j < cnt; j += 4) {
            int e = s_eid[j];
            float wt = s_lg[j * LSTR + h];
            float4 vv = __ldcs((const float4*)(v + (size_t)e * ROW + c * 4));
            acc.x += wt * vv.x;
            acc.y += wt * vv.y;
            acc.z += wt * vv.z;
            acc.w += wt * vv.w;
        }
    }
    s_red[tid] = acc;
    __syncthreads();
    if (tid < 64) {
        float4 a0 = s_red[tid];
        float4 a1 = s_red[tid + 64];
        float4 a2 = s_red[tid + 128];
        float4 a3 = s_red[tid + 192];
        float inv = s_inv[tid >> 3];
        float4 r;
        r.x = (a0.x + a1.x + a2.x + a3.x) * inv;
        r.y = (a0.y + a1.y + a2.y + a3.y) * inv;
        r.z = (a0.z + a1.z + a2.z + a3.z) * inv;
        r.w = (a0.w + a1.w + a2.w + a3.w) * inv;
        ((float4*)(out + (size_t)n * ROW))[tid] = r;
    }
}

// ---------------- launch ----------------

extern "C" void kernel_launch(void* const* d_in, const int* in_sizes, int n_in,
                              void* d_out, int out_size) {
    const float* v   = (const float*)d_in[0];
    const float* kk  = (const float*)d_in[1];
    const float* q   = (const float*)d_in[2];
    const int*   dst = (const int*)d_in[3];
    float* out = (float*)d_out;

    const int E = in_sizes[3];
    const int N = in_sizes[2] / ROW;

    k_scatter<<<(E + 1023) / 1024, 256>>>(dst, E);
    k_attn<<<N, 256>>>(v, kk, q, dst, out);
}

// round 16
// speedup vs baseline: 1.0375x; 1.0375x over previous
#include <cuda_runtime.h>
#include <cuda_bf16.h>
#include <math.h>

#define HEADS    8
#define ROW      256         // HEADS * 32 floats, both k and v rows
#define N_MAX    32768
#define SLOTS    256         // bucket slots per node (max expected degree ~55)
#define CAPX     320         // smem edge-id capacity
#define LSTR     9           // padded logit stride (gcd(9,32)=1 -> conflict-free)
#define OVF_MAX  8192

// Static device scratch (zero-initialized at module load; k_attn self-cleans
// g_count / g_ovf_cnt AFTER its first barrier so every launch starts zeroed).
__device__ int g_count[N_MAX];
__device__ int g_edges[(size_t)N_MAX * SLOTS];   // 20 MB bucketed edge ids
__device__ int g_ovf_cnt;
__device__ int g_ovf[OVF_MAX];

// ---------------- bucket build (single pass, 4 edges/thread) ----------------

__global__ void k_scatter(const int* __restrict__ dst, int E) {
    int i = (blockIdx.x * blockDim.x + threadIdx.x) * 4;
    if (i + 3 < E) {
        int4 d = *(const int4*)(dst + i);
        int p0 = atomicAdd(&g_count[d.x], 1);
        int p1 = atomicAdd(&g_count[d.y], 1);
        int p2 = atomicAdd(&g_count[d.z], 1);
        int p3 = atomicAdd(&g_count[d.w], 1);
        if (p0 < SLOTS) g_edges[(size_t)d.x * SLOTS + p0] = i;
        else { int o = atomicAdd(&g_ovf_cnt, 1); if (o < OVF_MAX) g_ovf[o] = i; }
        if (p1 < SLOTS) g_edges[(size_t)d.y * SLOTS + p1] = i + 1;
        else { int o = atomicAdd(&g_ovf_cnt, 1); if (o < OVF_MAX) g_ovf[o] = i + 1; }
        if (p2 < SLOTS) g_edges[(size_t)d.z * SLOTS + p2] = i + 2;
        else { int o = atomicAdd(&g_ovf_cnt, 1); if (o < OVF_MAX) g_ovf[o] = i + 2; }
        if (p3 < SLOTS) g_edges[(size_t)d.w * SLOTS + p3] = i + 3;
        else { int o = atomicAdd(&g_ovf_cnt, 1); if (o < OVF_MAX) g_ovf[o] = i + 3; }
    } else {
        for (int j = i; j < E; j++) {
            int d = dst[j];
            int p = atomicAdd(&g_count[d], 1);
            if (p < SLOTS) g_edges[(size_t)d * SLOTS + p] = j;
            else { int o = atomicAdd(&g_ovf_cnt, 1); if (o < OVF_MAX) g_ovf[o] = j; }
        }
    }
}

// ---------------- Main attention kernel ----------------
// One block (256 thr) per destination node. Best-measured configuration:
// Phase 1: warp-per-edge logits, 2-deep unroll (4x LDG.128 in flight/warp),
//          2-shfl segmented reduce vs register-resident q.
// Phase 2: single-pass softmax (no max subtraction: logits bounded ~|2.5|,
//          softmax is shift-invariant -> mathematically identical).
// Phase 3: float4-column value accumulation, 4-deep unroll
//          (4 independent LDG.128 in flight/thread), smem combine.

__global__ __launch_bounds__(256, 8)
void k_attn(const float* __restrict__ v, const float* __restrict__ kk,
            const float* __restrict__ q, const int* __restrict__ dst,
            float* __restrict__ out) {
    const int n   = blockIdx.x;
    const int tid = threadIdx.x;
    const int w   = tid >> 5;
    const int l   = tid & 31;

    __shared__ int    s_eid[CAPX];
    __shared__ float  s_lg[CAPX * LSTR];
    __shared__ float4 s_red[256];
    __shared__ float  s_inv[HEADS];
    __shared__ int    s_novf;

    const int cnt_raw = g_count[n];
    int cnt = (cnt_raw < SLOTS) ? cnt_raw : SLOTS;

    for (int j = tid; j < cnt; j += 256)
        s_eid[j] = g_edges[(size_t)n * SLOTS + j];

    if (__builtin_expect(cnt_raw > SLOTS, 0)) {
        // Overflow path: never taken for this data, kept for correctness.
        if (tid == 0) s_novf = 0;
        __syncthreads();
        int total = g_ovf_cnt;
        if (total > OVF_MAX) total = OVF_MAX;
        for (int o = tid; o < total; o += 256) {
            int e = g_ovf[o];
            if (dst[e] == n) {
                int p = atomicAdd(&s_novf, 1);
                if (cnt + p < CAPX) s_eid[cnt + p] = e;
            }
        }
        __syncthreads();
        int x = cnt + s_novf;
        cnt = (x < CAPX) ? x : CAPX;
    }
    __syncthreads();

    // Self-clean for next launch (all threads consumed g_count[n] already).
    if (tid == 0) {
        g_count[n] = 0;
        if (n == 0) g_ovf_cnt = 0;
    }

    // q row for this node, lane's 8-element slice (head = l>>2)
    const float* qp = q + (size_t)n * ROW + l * 8;
    const float4 q0 = *(const float4*)qp;
    const float4 q1 = *(const float4*)(qp + 4);

    // ---- Phase 1: logits (warp-per-edge, 2x LDG.128 + 2 shfl) ----
    {
        int j = w;
        for (; j + 8 < cnt; j += 16) {
            int ea = s_eid[j];
            int eb = s_eid[j + 8];
            const float4* ka = (const float4*)(kk + (size_t)ea * ROW + l * 8);
            const float4* kb = (const float4*)(kk + (size_t)eb * ROW + l * 8);
            float4 a0 = __ldcs(ka), a1 = __ldcs(ka + 1);
            float4 b0 = __ldcs(kb), b1 = __ldcs(kb + 1);
            float da = a0.x*q0.x + a0.y*q0.y + a0.z*q0.z + a0.w*q0.w
                     + a1.x*q1.x + a1.y*q1.y + a1.z*q1.z + a1.w*q1.w;
            float db = b0.x*q0.x + b0.y*q0.y + b0.z*q0.z + b0.w*q0.w
                     + b1.x*q1.x + b1.y*q1.y + b1.z*q1.z + b1.w*q1.w;
            da += __shfl_xor_sync(0xffffffffu, da, 1);
            da += __shfl_xor_sync(0xffffffffu, da, 2);
            db += __shfl_xor_sync(0xffffffffu, db, 1);
            db += __shfl_xor_sync(0xffffffffu, db, 2);
            if ((l & 3) == 0) {
                int h = l >> 2;
                s_lg[j * LSTR + h]       = da * 0.0625f;
                s_lg[(j + 8) * LSTR + h] = db * 0.0625f;
            }
        }
        for (; j < cnt; j += 8) {
            int e = s_eid[j];
            const float4* kr = (const float4*)(kk + (size_t)e * ROW + l * 8);
            float4 a0 = __ldcs(kr), a1 = __ldcs(kr + 1);
            float d = a0.x*q0.x + a0.y*q0.y + a0.z*q0.z + a0.w*q0.w
                    + a1.x*q1.x + a1.y*q1.y + a1.z*q1.z + a1.w*q1.w;
            d += __shfl_xor_sync(0xffffffffu, d, 1);
            d += __shfl_xor_sync(0xffffffffu, d, 2);
            if ((l & 3) == 0)
                s_lg[j * LSTR + (l >> 2)] = d * 0.0625f;
        }
    }
    __syncthreads();

    // ---- Phase 2: per-head softmax, single pass ----
    {
        float s = 0.f;
        for (int j = l; j < cnt; j += 32) {
            float e = __expf(s_lg[j * LSTR + w]);
            s_lg[j * LSTR + w] = e;
            s += e;
        }
        #pragma unroll
        for (int o = 16; o; o >>= 1)
            s += __shfl_xor_sync(0xffffffffu, s, o);
        if (l == 0) s_inv[w] = 1.f / fmaxf(s, 1e-9f);
    }
    __syncthreads();

    // ---- Phase 3: value accumulation (4 float4 loads in flight/thread) ----
    const int c  = tid & 63;   // float4 column within 256-float row
    const int eo = tid >> 6;   // edge offset 0..3
    const int h  = c >> 3;
    float4 acc = make_float4(0.f, 0.f, 0.f, 0.f);
    {
        int j = eo;
        for (; j + 12 < cnt; j += 16) {
            int e0 = s_eid[j];
            int e1 = s_eid[j + 4];
            int e2 = s_eid[j + 8];
            int e3 = s_eid[j + 12];
            float w0 = s_lg[j * LSTR + h];
            float w1 = s_lg[(j + 4) * LSTR + h];
            float w2 = s_lg[(j + 8) * LSTR + h];
            float w3 = s_lg[(j + 12) * LSTR + h];
            float4 v0 = __ldcs((const float4*)(v + (size_t)e0 * ROW + c * 4));
            float4 v1 = __ldcs((const float4*)(v + (size_t)e1 * ROW + c * 4));
            float4 v2 = __ldcs((const float4*)(v + (size_t)e2 * ROW + c * 4));
            float4 v3 = __ldcs((const float4*)(v + (size_t)e3 * ROW + c * 4));
            acc.x += w0 * v0.x + w1 * v1.x + w2 * v2.x + w3 * v3.x;
            acc.y += w0 * v0.y + w1 * v1.y + w2 * v2.y + w3 * v3.y;
            acc.z += w0 * v0.z + w1 * v1.z + w2 * v2.z + w3 * v3.z;
            acc.w += w0 * v0.w + w1 * v1.w + w2 * v2.w + w3 * v3.w;
        }
        for (; j + 4 < cnt; j += 8) {
            int ea = s_eid[j];
            int eb = s_eid[j + 4];
            float wa = s_lg[j * LSTR + h];
            float wb = s_lg[(j + 4) * LSTR + h];
            float4 va = __ldcs((const float4*)(v + (size_t)ea * ROW + c * 4));
            float4 vb = __ldcs((const float4*)(v + (size_t)eb * ROW + c * 4));
            acc.x += wa * va.x + wb * vb.x;
            acc.y += wa * va.y + wb * vb.y;
            acc.z += wa * va.z + wb * vb.z;
            acc.w += wa * va.w + wb * vb.w;
        }
        for (; j < cnt; j += 4) {
            int e = s_eid[j];
            float wt = s_lg[j * LSTR + h];
            float4 vv = __ldcs((const float4*)(v + (size_t)e * ROW + c * 4));
            acc.x += wt * vv.x;
            acc.y += wt * vv.y;
            acc.z += wt * vv.z;
            acc.w += wt * vv.w;
        }
    }
    s_red[tid] = acc;
    __syncthreads();
    if (tid < 64) {
        float4 a0 = s_red[tid];
        float4 a1 = s_red[tid + 64];
        float4 a2 = s_red[tid + 128];
        float4 a3 = s_red[tid + 192];
        float inv = s_inv[tid >> 3];
        float4 r;
        r.x = (a0.x + a1.x + a2.x + a3.x) * inv;
        r.y = (a0.y + a1.y + a2.y + a3.y) * inv;
        r.z = (a0.z + a1.z + a2.z + a3.z) * inv;
        r.w = (a0.w + a1.w + a2.w + a3.w) * inv;
        ((float4*)(out + (size_t)n * ROW))[tid] = r;
    }
}

// ---------------- launch ----------------

extern "C" void kernel_launch(void* const* d_in, const int* in_sizes, int n_in,
                              void* d_out, int out_size) {
    const float* v   = (const float*)d_in[0];
    const float* kk  = (const float*)d_in[1];
    const float* q   = (const float*)d_in[2];
    const int*   dst = (const int*)d_in[3];
    float* out = (float*)d_out;

    const int E = in_sizes[3];
    const int N = in_sizes[2] / ROW;

    k_scatter<<<(E + 1023) / 1024, 256>>>(dst, E);
    k_attn<<<N, 256>>>(v, kk, q, dst, out);
}